// round 11
// baseline (speedup 1.0000x reference)
#include <cuda_runtime.h>
#include <math.h>

#define NS 2048
#define NR 2048
#define KNB 5
#define NBINS 1024
#define CAP 65536
#define KEYS_CAP 4096
#define MAXIDX 104857599u
// float32 nearest to python 0.1**2
#define SIG2F 0.009999999776482582f

__device__ float    g_sd[NS*KNB];
__device__ int      g_sidx[NS*KNB];
__device__ float    g_rdT[KNB*NR];
__device__ int      g_ridxT[KNB*NR];
__device__ unsigned g_hist[NBINS];
__device__ unsigned g_ccount;
__device__ float    g_thr;
__device__ float    g_cval[CAP];
__device__ int      g_cidx[CAP];

__global__ void zero_kernel() {
    int t = blockIdx.x * blockDim.x + threadIdx.x;
    if (t < NBINS) g_hist[t] = 0;
    if (t == 0) g_ccount = 0;
}

// FMA-CONTRACTED squared distance — XLA (GPU, and aarch64 LLVM by default)
// contracts the square-and-reduce into an fma chain:
//   d2 = fma(dz, dz, fma(dy, dy, dx*dx))
__device__ __forceinline__ float d2_ref(float dx, float dy, float dz) {
    return __fmaf_rn(dz, dz, __fmaf_rn(dy, dy, __fmul_rn(dx, dx)));
}

// Brute-force KNN: one block per point. Ranks candidates by the f32-rounded
// distance (jax's top_k(-cdist) key), tie-break by smaller index. Keeps
// top-6, drops slot 0 (self).
__global__ __launch_bounds__(128) void knn_kernel(const float* __restrict__ pts,
                                                  int n, int mode) {
    __shared__ float sx[2048], sy[2048], sz[2048];
    __shared__ float cd[128 * 6];
    __shared__ int   ci[128 * 6];
    int p = blockIdx.x, tid = threadIdx.x;
    for (int j = tid; j < n; j += 128) {
        sx[j] = pts[j * 3 + 0];
        sy[j] = pts[j * 3 + 1];
        sz[j] = pts[j * 3 + 2];
    }
    __syncthreads();
    float px = sx[p], py = sy[p], pz = sz[p];
    float bd[6]; int bi[6];
#pragma unroll
    for (int q = 0; q < 6; q++) { bd[q] = 3.4e38f; bi[q] = 0x7fffffff; }
    for (int j = tid; j < n; j += 128) {
        float d2 = d2_ref(sx[j] - px, sy[j] - py, sz[j] - pz);
        float dist = __fsqrt_rn(fmaxf(d2, 0.0f));   // jax's ranking key
        if (dist < bd[5] || (dist == bd[5] && j < bi[5])) {
            bd[5] = dist; bi[5] = j;
#pragma unroll
            for (int q = 5; q > 0; q--) {
                if (bd[q] < bd[q-1] || (bd[q] == bd[q-1] && bi[q] < bi[q-1])) {
                    float td = bd[q]; bd[q] = bd[q-1]; bd[q-1] = td;
                    int   ti = bi[q]; bi[q] = bi[q-1]; bi[q-1] = ti;
                }
            }
        }
    }
#pragma unroll
    for (int q = 0; q < 6; q++) { cd[tid * 6 + q] = bd[q]; ci[tid * 6 + q] = bi[q]; }
    __syncthreads();
    if (tid == 0) {
        float fd[6]; int fi[6];
#pragma unroll
        for (int q = 0; q < 6; q++) { fd[q] = 3.4e38f; fi[q] = 0x7fffffff; }
        for (int c = 0; c < 128 * 6; c++) {
            float dist = cd[c]; int id = ci[c];
            if (dist < fd[5] || (dist == fd[5] && id < fi[5])) {
                fd[5] = dist; fi[5] = id;
                for (int q = 5; q > 0; q--) {
                    if (fd[q] < fd[q-1] || (fd[q] == fd[q-1] && fi[q] < fi[q-1])) {
                        float td = fd[q]; fd[q] = fd[q-1]; fd[q-1] = td;
                        int   ti = fi[q]; fi[q] = fi[q-1]; fi[q-1] = ti;
                    }
                }
            }
        }
        for (int c = 1; c < 6; c++) {   // drop self (slot 0)
            int ni = fi[c]; if (ni < 0) ni = 0; if (ni >= n) ni = n - 1;
            float dist = fd[c];          // the f32 sqrt value (norm result)
            if (mode == 0) {
                g_sd[p * KNB + c - 1]   = dist;
                g_sidx[p * KNB + c - 1] = ni;
            } else {
                g_rdT[(c - 1) * NR + p]   = dist;
                g_ridxT[(c - 1) * NR + p] = ni;
            }
        }
    }
}

// Scan 1: exact 1024-bin histogram of the hot-loop value over all 104.8M
// combos. One block per s; 5 gather rows staged in SMEM (static 44KB).
__global__ __launch_bounds__(256) void hist_kernel(const float* __restrict__ aff) {
    __shared__ float    rows[KNB][2048];
    __shared__ unsigned hist[NBINS];
    __shared__ int      s_sidx[KNB];
    int s = blockIdx.x, tid = threadIdx.x;
    if (tid < KNB) s_sidx[tid] = g_sidx[s * KNB + tid];
    for (int b = tid; b < NBINS; b += 256) hist[b] = 0;
    __syncthreads();
#pragma unroll
    for (int i = 0; i < KNB; i++) {
        const float4* srcp = (const float4*)(aff + s_sidx[i] * NR);
        float4* dst = (float4*)rows[i];
        for (int c = tid; c < 512; c += 256) dst[c] = srcp[c];
    }
    float sdv[KNB];
#pragma unroll
    for (int i = 0; i < KNB; i++) sdv[i] = g_sd[s * KNB + i];
    __syncthreads();

    for (int rb = 0; rb < NR; rb += 256) {
        int r = rb + tid;
        float base = aff[s * NR + r];
        float b100 = -100.0f * base;
        float rd[KNB]; int ra[KNB];
#pragma unroll
        for (int j = 0; j < KNB; j++) {
            rd[j] = g_rdT[j * NR + r];
            ra[j] = g_ridxT[j * NR + r];
        }
#pragma unroll
        for (int i = 0; i < KNB; i++) {
#pragma unroll
            for (int j = 0; j < KNB; j++) {
                float d  = sdv[i] - rd[j];
                float bt = __fmaf_rn(__fmul_rn(d, d), b100, base);
                float v  = __fmul_rn(bt, rows[i][ra[j]]);
                if (v > 0.0f) {
                    int bin = (int)(v * 1024.0f);   // exact power-of-two binning
                    if (bin > NBINS - 1) bin = NBINS - 1;
                    atomicAdd(&hist[bin], 1u);
                }
            }
        }
    }
    __syncthreads();
    for (int b = tid; b < NBINS; b += 256) {
        unsigned c = hist[b];
        if (c) atomicAdd(&g_hist[b], c);
    }
}

// Exact threshold: bin of the 512th-largest hot value, admission edge one
// bin lower; admitted count known exactly and forced <= CAP.
__global__ void thresh_kernel() {
    if (threadIdx.x == 0 && blockIdx.x == 0) {
        unsigned suf = 0; int bstar = -1;
        for (int b = NBINS - 1; b >= 0; b--) {
            suf += g_hist[b];
            if (suf >= 512) { bstar = b; break; }
        }
        if (bstar < 0) bstar = 0;
        int ba = bstar > 0 ? bstar - 1 : 0;            // one-bin slack
        unsigned cnt = suf + ((ba < bstar) ? g_hist[ba] : 0u);
        while (cnt > CAP && ba < NBINS - 1) {          // force admitted <= CAP
            cnt -= g_hist[ba];
            ba++;
        }
        g_thr = (float)ba * (1.0f / 1024.0f);          // exact lower bin edge
    }
}

// Scan 2: admit hot value v >= thr (bit-consistent with histogram predicate);
// store FAITHFUL XLA-exact value + flat index.
__global__ __launch_bounds__(256) void collect_kernel(const float* __restrict__ aff) {
    __shared__ float rows[KNB][2048];
    __shared__ int   s_sidx[KNB];
    int s = blockIdx.x, tid = threadIdx.x;
    if (tid < KNB) s_sidx[tid] = g_sidx[s * KNB + tid];
    __syncthreads();
#pragma unroll
    for (int i = 0; i < KNB; i++) {
        const float4* srcp = (const float4*)(aff + s_sidx[i] * NR);
        float4* dst = (float4*)rows[i];
        for (int c = tid; c < 512; c += 256) dst[c] = srcp[c];
    }
    float thr = g_thr;
    float sdv[KNB];
#pragma unroll
    for (int i = 0; i < KNB; i++) sdv[i] = g_sd[s * KNB + i];
    __syncthreads();
    for (int rb = 0; rb < NR; rb += 256) {
        int r = rb + tid;
        float base = aff[s * NR + r];
        float b100 = -100.0f * base;
        float rd[KNB]; int ra[KNB];
#pragma unroll
        for (int j = 0; j < KNB; j++) {
            rd[j] = g_rdT[j * NR + r];
            ra[j] = g_ridxT[j * NR + r];
        }
#pragma unroll
        for (int i = 0; i < KNB; i++) {
#pragma unroll
            for (int j = 0; j < KNB; j++) {
                float d  = sdv[i] - rd[j];
                float dd = __fmul_rn(d, d);
                float bt = __fmaf_rn(dd, b100, base);
                if (bt >= thr) {                       // rows < 1 => v <= bt
                    float v = __fmul_rn(bt, rows[i][ra[j]]);
                    if (v >= thr && v > 0.0f) {
                        // faithful XLA-exact value for ranking
                        float q   = __fdiv_rn(dd, SIG2F);
                        float tmp = __fadd_rn(1.0f, -q);
                        tmp = fmaxf(tmp, 0.0f);
                        float vf = __fmul_rn(__fmul_rn(base, tmp), rows[i][ra[j]]);
                        unsigned pos = atomicAdd(&g_ccount, 1u);
                        if (pos < CAP) {
                            g_cval[pos] = vf;
                            g_cidx[pos] = (s * NR + r) * 25 + i * 5 + j;
                        }
                    }
                }
            }
        }
    }
}

// Select: (optional refine to <=KEYS_CAP with EXACT capacity check) ->
// bitonic sort (faithful value desc, index asc) -> emit indices as float32.
__global__ __launch_bounds__(1024) void select_kernel(float* __restrict__ out,
                                                      int out_size) {
    __shared__ unsigned long long keys[KEYS_CAP];
    __shared__ unsigned h2[1024];
    __shared__ unsigned m2;
    __shared__ float sh_thr2;
    int tid = threadIdx.x;
    unsigned M = g_ccount; if (M > CAP) M = CAP;
    float thr = g_thr;
    h2[tid] = 0;
    if (tid == 0) { m2 = 0; sh_thr2 = -1.0f; }
    __syncthreads();
    if (M > KEYS_CAP) {
        float binw2 = (1.0f - thr) * (1.0f / 1024.0f);
        if (binw2 <= 0.0f) binw2 = 1e-9f;
        for (unsigned c = tid; c < M; c += 1024) {
            float v = g_cval[c];
            int b = (int)((v - thr) / binw2);
            if (b < 0) b = 0;
            if (b > 1023) b = 1023;
            atomicAdd(&h2[b], 1u);
        }
        __syncthreads();
        if (tid == 0) {
            unsigned suf = 0; int b2 = 0;
            for (int b = 1023; b >= 0; b--) {
                suf += h2[b];
                if (suf >= 512) { b2 = b; break; }
            }
            // include one slack bin ONLY if survivors provably fit in keys[]
            int ba = b2;
            unsigned cnt = suf;
            if (ba > 0 && cnt + h2[ba - 1] <= (unsigned)KEYS_CAP) {
                ba--; cnt += h2[ba];
            }
            while (cnt > (unsigned)KEYS_CAP && ba < 1023) { // paranoid shrink
                cnt -= h2[ba]; ba++;
            }
            sh_thr2 = thr + (float)ba * binw2;
            if (sh_thr2 < thr) sh_thr2 = thr;
        }
        __syncthreads();
    }
    float thr2 = sh_thr2;   // -1 => keep all
    for (unsigned c = tid; c < M; c += 1024) {
        float v = g_cval[c];
        if (v >= thr2) {
            unsigned p = atomicAdd(&m2, 1u);
            if (p < KEYS_CAP) {
                unsigned idx = (unsigned)g_cidx[c];
                if (idx > MAXIDX) idx = MAXIDX;
                keys[p] = ((unsigned long long)__float_as_uint(v) << 32)
                        | (unsigned long long)(0xFFFFFFFFu - idx);
            }
        }
    }
    __syncthreads();
    unsigned M2 = m2; if (M2 > KEYS_CAP) M2 = KEYS_CAP;
    for (unsigned e = M2 + tid; e < KEYS_CAP; e += 1024) keys[e] = 0ull;
    __syncthreads();
    for (unsigned k = 2; k <= KEYS_CAP; k <<= 1) {
        for (unsigned jj = k >> 1; jj > 0; jj >>= 1) {
            for (unsigned e = tid; e < KEYS_CAP; e += 1024) {
                unsigned partner = e ^ jj;
                if (partner > e) {
                    unsigned long long A = keys[e], B = keys[partner];
                    bool desc = ((e & k) == 0);
                    if (desc ? (A < B) : (A > B)) { keys[e] = B; keys[partner] = A; }
                }
            }
            __syncthreads();
        }
    }
    if (tid < 512) {
        unsigned long long key = keys[tid];
        unsigned idx = 0xFFFFFFFFu - (unsigned)(key & 0xFFFFFFFFull);
        if (idx > MAXIDX) idx = MAXIDX;                 // in-range by force
        int s = (int)(idx / 51200u);  int rem = (int)(idx - (unsigned)s * 51200u);
        int r = rem / 25;             int ij  = rem - r * 25;
        int i = ij / 5;               int j   = ij - i * 5;
        if (s > NS - 1) s = NS - 1;
        if (r > NR - 1) r = NR - 1;
        // __output__ is float32: (4,512) stacked index arrays as floats.
        if (tid < out_size)        out[tid]        = (float)s;
        if (512 + tid < out_size)  out[512 + tid]  = (float)r;
        if (1024 + tid < out_size) out[1024 + tid] = (float)g_sidx[s * KNB + i];
        if (1536 + tid < out_size) out[1536 + tid] = (float)g_ridxT[j * NR + r];
    }
}

extern "C" void kernel_launch(void* const* d_in, const int* in_sizes, int n_in,
                              void* d_out, int out_size) {
    // Dual-path binding: dict order (src, ref, aff) or alphabetical
    // (aff, ref, src); discriminate by the unique large affinity size.
    const float *src, *ref, *aff;
    if (in_sizes[0] >= (1 << 20)) {
        aff = (const float*)d_in[0];
        ref = (const float*)d_in[1];
        src = (const float*)d_in[2];
    } else {
        src = (const float*)d_in[0];
        ref = (const float*)d_in[1];
        aff = (const float*)d_in[2];
    }
    float* out = (float*)d_out;

    zero_kernel<<<4, 256>>>();
    knn_kernel<<<NS, 128>>>(src, NS, 0);
    knn_kernel<<<NR, 128>>>(ref, NR, 1);
    hist_kernel<<<NS, 256>>>(aff);
    thresh_kernel<<<1, 32>>>();
    collect_kernel<<<NS, 256>>>(aff);
    select_kernel<<<1, 1024>>>(out, out_size);
}

// round 12
// speedup vs baseline: 1.2110x; 1.2110x over previous
#include <cuda_runtime.h>
#include <math.h>

#define NS 2048
#define NR 2048
#define KNB 5
#define NBINS 1024
#define RFLOOR 512                 // scan1 bins only v >= 0.5 (bin 512+)
#define COLLECT_BIN 993
#define COLLECT_THR 0.9697265625f  // 993/1024, exact bin edge
#define CAP 65536
#define KEYS_CAP 4096
#define MAXIDX 104857599u
// float32 nearest to python 0.1**2
#define SIG2F 0.009999999776482582f

__device__ float    g_sd[NS*KNB];
__device__ int      g_sidx[NS*KNB];
__device__ float    g_rdT[KNB*NR];
__device__ int      g_ridxT[KNB*NR];
__device__ unsigned g_hist[NBINS];
__device__ unsigned g_ccount;
__device__ float    g_thr;
__device__ int      g_skip;
__device__ int      g_need_full;
__device__ float    g_cval[CAP];
__device__ int      g_cidx[CAP];

__global__ void zero_kernel() {
    int t = blockIdx.x * blockDim.x + threadIdx.x;
    if (t < NBINS) g_hist[t] = 0;
    if (t == 0) { g_ccount = 0; g_need_full = 0; g_skip = 0; }
}

// FMA-CONTRACTED squared distance — matches XLA's contraction (verified R11).
__device__ __forceinline__ float d2_ref(float dx, float dy, float dz) {
    return __fmaf_rn(dz, dz, __fmaf_rn(dy, dy, __fmul_rn(dx, dx)));
}

// Brute-force KNN (unchanged from the passing R11 kernel).
__global__ __launch_bounds__(128) void knn_kernel(const float* __restrict__ pts,
                                                  int n, int mode) {
    __shared__ float sx[2048], sy[2048], sz[2048];
    __shared__ float cd[128 * 6];
    __shared__ int   ci[128 * 6];
    int p = blockIdx.x, tid = threadIdx.x;
    for (int j = tid; j < n; j += 128) {
        sx[j] = pts[j * 3 + 0];
        sy[j] = pts[j * 3 + 1];
        sz[j] = pts[j * 3 + 2];
    }
    __syncthreads();
    float px = sx[p], py = sy[p], pz = sz[p];
    float bd[6]; int bi[6];
#pragma unroll
    for (int q = 0; q < 6; q++) { bd[q] = 3.4e38f; bi[q] = 0x7fffffff; }
    for (int j = tid; j < n; j += 128) {
        float d2 = d2_ref(sx[j] - px, sy[j] - py, sz[j] - pz);
        float dist = __fsqrt_rn(fmaxf(d2, 0.0f));   // jax's ranking key
        if (dist < bd[5] || (dist == bd[5] && j < bi[5])) {
            bd[5] = dist; bi[5] = j;
#pragma unroll
            for (int q = 5; q > 0; q--) {
                if (bd[q] < bd[q-1] || (bd[q] == bd[q-1] && bi[q] < bi[q-1])) {
                    float td = bd[q]; bd[q] = bd[q-1]; bd[q-1] = td;
                    int   ti = bi[q]; bi[q] = bi[q-1]; bi[q-1] = ti;
                }
            }
        }
    }
#pragma unroll
    for (int q = 0; q < 6; q++) { cd[tid * 6 + q] = bd[q]; ci[tid * 6 + q] = bi[q]; }
    __syncthreads();
    if (tid == 0) {
        float fd[6]; int fi[6];
#pragma unroll
        for (int q = 0; q < 6; q++) { fd[q] = 3.4e38f; fi[q] = 0x7fffffff; }
        for (int c = 0; c < 128 * 6; c++) {
            float dist = cd[c]; int id = ci[c];
            if (dist < fd[5] || (dist == fd[5] && id < fi[5])) {
                fd[5] = dist; fi[5] = id;
                for (int q = 5; q > 0; q--) {
                    if (fd[q] < fd[q-1] || (fd[q] == fd[q-1] && fi[q] < fi[q-1])) {
                        float td = fd[q]; fd[q] = fd[q-1]; fd[q-1] = td;
                        int   ti = fi[q]; fi[q] = fi[q-1]; fi[q-1] = ti;
                    }
                }
            }
        }
        for (int c = 1; c < 6; c++) {   // drop self (slot 0)
            int ni = fi[c]; if (ni < 0) ni = 0; if (ni >= n) ni = n - 1;
            float dist = fd[c];
            if (mode == 0) {
                g_sd[p * KNB + c - 1]   = dist;
                g_sidx[p * KNB + c - 1] = ni;
            } else {
                g_rdT[(c - 1) * NR + p]   = dist;
                g_ridxT[(c - 1) * NR + p] = ni;
            }
        }
    }
}

// SINGLE SCAN: histogram restricted to v >= 0.5 (bins 512..1023) +
// opportunistic candidate collection at v >= 993/1024 storing faithful values.
__global__ __launch_bounds__(256) void scan1_kernel(const float* __restrict__ aff) {
    __shared__ float    rows[KNB][2048];
    __shared__ unsigned hist[NBINS - RFLOOR];
    __shared__ int      s_sidx[KNB];
    int s = blockIdx.x, tid = threadIdx.x;
    if (tid < KNB) s_sidx[tid] = g_sidx[s * KNB + tid];
    for (int b = tid; b < NBINS - RFLOOR; b += 256) hist[b] = 0;
    __syncthreads();
#pragma unroll
    for (int i = 0; i < KNB; i++) {
        const float4* srcp = (const float4*)(aff + s_sidx[i] * NR);
        float4* dst = (float4*)rows[i];
        for (int c = tid; c < 512; c += 256) dst[c] = srcp[c];
    }
    float sdv[KNB];
#pragma unroll
    for (int i = 0; i < KNB; i++) sdv[i] = g_sd[s * KNB + i];
    __syncthreads();

    for (int rb = 0; rb < NR; rb += 256) {
        int r = rb + tid;
        float base = aff[s * NR + r];
        float b100 = -100.0f * base;
        float rd[KNB]; int ra[KNB];
#pragma unroll
        for (int j = 0; j < KNB; j++) {
            rd[j] = g_rdT[j * NR + r];
            ra[j] = g_ridxT[j * NR + r];
        }
#pragma unroll
        for (int i = 0; i < KNB; i++) {
#pragma unroll
            for (int j = 0; j < KNB; j++) {
                float d  = sdv[i] - rd[j];
                float dd = __fmul_rn(d, d);
                float bt = __fmaf_rn(dd, b100, base);
                float v  = __fmul_rn(bt, rows[i][ra[j]]);
                if (v >= 0.5f) {
                    int bin = (int)(v * 1024.0f);   // exact power-of-two binning
                    if (bin > NBINS - 1) bin = NBINS - 1;
                    atomicAdd(&hist[bin - RFLOOR], 1u);
                    if (v >= COLLECT_THR) {
                        float q   = __fdiv_rn(dd, SIG2F);
                        float tmp = __fadd_rn(1.0f, -q);
                        tmp = fmaxf(tmp, 0.0f);
                        float vf = __fmul_rn(__fmul_rn(base, tmp), rows[i][ra[j]]);
                        unsigned pos = atomicAdd(&g_ccount, 1u);
                        if (pos < CAP) {
                            g_cval[pos] = vf;
                            g_cidx[pos] = (s * NR + r) * 25 + i * 5 + j;
                        }
                    }
                }
            }
        }
    }
    __syncthreads();
    for (int b = tid; b < NBINS - RFLOOR; b += 256) {
        unsigned c = hist[b];
        if (c) atomicAdd(&g_hist[RFLOOR + b], c);
    }
}

// Threshold from the restricted histogram. If the 512th value can't be
// resolved above the floor (or slack would dip below it), request the full
// low-bin histogram instead of guessing.
__global__ void thresh_kernel() {
    if (threadIdx.x == 0 && blockIdx.x == 0) {
        unsigned suf = 0; int bstar = -1;
        for (int b = NBINS - 1; b >= RFLOOR; b--) {
            suf += g_hist[b];
            if (suf >= 512) { bstar = b; break; }
        }
        if (bstar <= RFLOOR) {          // unresolved, or slack below floor
            g_need_full = 1;
            g_skip = 0;
            return;
        }
        int ba = bstar - 1;             // one-bin slack (>= RFLOOR, counted)
        unsigned cnt = suf + g_hist[ba];
        while (cnt > CAP && ba < NBINS - 1) {
            cnt -= g_hist[ba];
            ba++;
        }
        g_thr = (float)ba * (1.0f / 1024.0f);
        int skip = (ba >= COLLECT_BIN && g_ccount <= CAP) ? 1 : 0;
        g_skip = skip;
        if (!skip) g_ccount = 0;        // fallback collect recollects fresh
    }
}

// Conditional: fill bins [0, RFLOOR) — only runs when thresh couldn't resolve.
__global__ __launch_bounds__(256) void hist_low_kernel(const float* __restrict__ aff) {
    if (!g_need_full) return;
    __shared__ float    rows[KNB][2048];
    __shared__ unsigned hist[RFLOOR];
    __shared__ int      s_sidx[KNB];
    int s = blockIdx.x, tid = threadIdx.x;
    if (tid < KNB) s_sidx[tid] = g_sidx[s * KNB + tid];
    for (int b = tid; b < RFLOOR; b += 256) hist[b] = 0;
    __syncthreads();
#pragma unroll
    for (int i = 0; i < KNB; i++) {
        const float4* srcp = (const float4*)(aff + s_sidx[i] * NR);
        float4* dst = (float4*)rows[i];
        for (int c = tid; c < 512; c += 256) dst[c] = srcp[c];
    }
    float sdv[KNB];
#pragma unroll
    for (int i = 0; i < KNB; i++) sdv[i] = g_sd[s * KNB + i];
    __syncthreads();
    for (int rb = 0; rb < NR; rb += 256) {
        int r = rb + tid;
        float base = aff[s * NR + r];
        float b100 = -100.0f * base;
        float rd[KNB]; int ra[KNB];
#pragma unroll
        for (int j = 0; j < KNB; j++) {
            rd[j] = g_rdT[j * NR + r];
            ra[j] = g_ridxT[j * NR + r];
        }
#pragma unroll
        for (int i = 0; i < KNB; i++) {
#pragma unroll
            for (int j = 0; j < KNB; j++) {
                float d  = sdv[i] - rd[j];
                float bt = __fmaf_rn(__fmul_rn(d, d), b100, base);
                float v  = __fmul_rn(bt, rows[i][ra[j]]);
                if (v > 0.0f && v < 0.5f) {
                    int bin = (int)(v * 1024.0f);
                    if (bin < RFLOOR) atomicAdd(&hist[bin], 1u);
                }
            }
        }
    }
    __syncthreads();
    for (int b = tid; b < RFLOOR; b += 256) {
        unsigned c = hist[b];
        if (c) atomicAdd(&g_hist[b], c);
    }
}

// Conditional: re-threshold over the now-complete histogram.
__global__ void thresh2_kernel() {
    if (threadIdx.x == 0 && blockIdx.x == 0) {
        if (!g_need_full) return;
        unsigned suf = 0; int bstar = -1;
        for (int b = NBINS - 1; b >= 0; b--) {
            suf += g_hist[b];
            if (suf >= 512) { bstar = b; break; }
        }
        if (bstar < 0) bstar = 0;
        int ba = bstar > 0 ? bstar - 1 : 0;
        unsigned cnt = suf + ((ba < bstar) ? g_hist[ba] : 0u);
        while (cnt > CAP && ba < NBINS - 1) {
            cnt -= g_hist[ba];
            ba++;
        }
        g_thr = (float)ba * (1.0f / 1024.0f);
        if (g_thr < 1e-30f) g_thr = 1e-30f;
        g_skip = 0;
        g_ccount = 0;
    }
}

// Fallback collect (usually skipped): admit hot v >= thr, store faithful value.
__global__ __launch_bounds__(256) void collect_kernel(const float* __restrict__ aff) {
    if (g_skip) return;
    __shared__ float rows[KNB][2048];
    __shared__ int   s_sidx[KNB];
    int s = blockIdx.x, tid = threadIdx.x;
    if (tid < KNB) s_sidx[tid] = g_sidx[s * KNB + tid];
    __syncthreads();
#pragma unroll
    for (int i = 0; i < KNB; i++) {
        const float4* srcp = (const float4*)(aff + s_sidx[i] * NR);
        float4* dst = (float4*)rows[i];
        for (int c = tid; c < 512; c += 256) dst[c] = srcp[c];
    }
    float thr = g_thr;
    float sdv[KNB];
#pragma unroll
    for (int i = 0; i < KNB; i++) sdv[i] = g_sd[s * KNB + i];
    __syncthreads();
    for (int rb = 0; rb < NR; rb += 256) {
        int r = rb + tid;
        float base = aff[s * NR + r];
        float b100 = -100.0f * base;
        float rd[KNB]; int ra[KNB];
#pragma unroll
        for (int j = 0; j < KNB; j++) {
            rd[j] = g_rdT[j * NR + r];
            ra[j] = g_ridxT[j * NR + r];
        }
#pragma unroll
        for (int i = 0; i < KNB; i++) {
#pragma unroll
            for (int j = 0; j < KNB; j++) {
                float d  = sdv[i] - rd[j];
                float dd = __fmul_rn(d, d);
                float bt = __fmaf_rn(dd, b100, base);
                if (bt >= thr) {
                    float v = __fmul_rn(bt, rows[i][ra[j]]);
                    if (v >= thr && v > 0.0f) {
                        float q   = __fdiv_rn(dd, SIG2F);
                        float tmp = __fadd_rn(1.0f, -q);
                        tmp = fmaxf(tmp, 0.0f);
                        float vf = __fmul_rn(__fmul_rn(base, tmp), rows[i][ra[j]]);
                        unsigned pos = atomicAdd(&g_ccount, 1u);
                        if (pos < CAP) {
                            g_cval[pos] = vf;
                            g_cidx[pos] = (s * NR + r) * 25 + i * 5 + j;
                        }
                    }
                }
            }
        }
    }
}

// Select (unchanged from passing R11): refine -> bitonic -> emit f32 indices.
__global__ __launch_bounds__(1024) void select_kernel(float* __restrict__ out,
                                                      int out_size) {
    __shared__ unsigned long long keys[KEYS_CAP];
    __shared__ unsigned h2[1024];
    __shared__ unsigned m2;
    __shared__ float sh_thr2;
    int tid = threadIdx.x;
    unsigned M = g_ccount; if (M > CAP) M = CAP;
    float thr = g_thr;
    h2[tid] = 0;
    if (tid == 0) { m2 = 0; sh_thr2 = -1.0f; }
    __syncthreads();
    if (M > KEYS_CAP) {
        float binw2 = (1.0f - thr) * (1.0f / 1024.0f);
        if (binw2 <= 0.0f) binw2 = 1e-9f;
        for (unsigned c = tid; c < M; c += 1024) {
            float v = g_cval[c];
            int b = (int)((v - thr) / binw2);
            if (b < 0) b = 0;
            if (b > 1023) b = 1023;
            atomicAdd(&h2[b], 1u);
        }
        __syncthreads();
        if (tid == 0) {
            unsigned suf = 0; int b2 = 0;
            for (int b = 1023; b >= 0; b--) {
                suf += h2[b];
                if (suf >= 512) { b2 = b; break; }
            }
            int ba = b2;
            unsigned cnt = suf;
            if (ba > 0 && cnt + h2[ba - 1] <= (unsigned)KEYS_CAP) {
                ba--; cnt += h2[ba];
            }
            while (cnt > (unsigned)KEYS_CAP && ba < 1023) {
                cnt -= h2[ba]; ba++;
            }
            sh_thr2 = thr + (float)ba * binw2;
            if (sh_thr2 < thr) sh_thr2 = thr;
        }
        __syncthreads();
    }
    float thr2 = sh_thr2;   // -1 => keep all
    for (unsigned c = tid; c < M; c += 1024) {
        float v = g_cval[c];
        if (v >= thr2) {
            unsigned p = atomicAdd(&m2, 1u);
            if (p < KEYS_CAP) {
                unsigned idx = (unsigned)g_cidx[c];
                if (idx > MAXIDX) idx = MAXIDX;
                keys[p] = ((unsigned long long)__float_as_uint(v) << 32)
                        | (unsigned long long)(0xFFFFFFFFu - idx);
            }
        }
    }
    __syncthreads();
    unsigned M2 = m2; if (M2 > KEYS_CAP) M2 = KEYS_CAP;
    for (unsigned e = M2 + tid; e < KEYS_CAP; e += 1024) keys[e] = 0ull;
    __syncthreads();
    for (unsigned k = 2; k <= KEYS_CAP; k <<= 1) {
        for (unsigned jj = k >> 1; jj > 0; jj >>= 1) {
            for (unsigned e = tid; e < KEYS_CAP; e += 1024) {
                unsigned partner = e ^ jj;
                if (partner > e) {
                    unsigned long long A = keys[e], B = keys[partner];
                    bool desc = ((e & k) == 0);
                    if (desc ? (A < B) : (A > B)) { keys[e] = B; keys[partner] = A; }
                }
            }
            __syncthreads();
        }
    }
    if (tid < 512) {
        unsigned long long key = keys[tid];
        unsigned idx = 0xFFFFFFFFu - (unsigned)(key & 0xFFFFFFFFull);
        if (idx > MAXIDX) idx = MAXIDX;
        int s = (int)(idx / 51200u);  int rem = (int)(idx - (unsigned)s * 51200u);
        int r = rem / 25;             int ij  = rem - r * 25;
        int i = ij / 5;               int j   = ij - i * 5;
        if (s > NS - 1) s = NS - 1;
        if (r > NR - 1) r = NR - 1;
        if (tid < out_size)        out[tid]        = (float)s;
        if (512 + tid < out_size)  out[512 + tid]  = (float)r;
        if (1024 + tid < out_size) out[1024 + tid] = (float)g_sidx[s * KNB + i];
        if (1536 + tid < out_size) out[1536 + tid] = (float)g_ridxT[j * NR + r];
    }
}

extern "C" void kernel_launch(void* const* d_in, const int* in_sizes, int n_in,
                              void* d_out, int out_size) {
    const float *src, *ref, *aff;
    if (in_sizes[0] >= (1 << 20)) {
        aff = (const float*)d_in[0];
        ref = (const float*)d_in[1];
        src = (const float*)d_in[2];
    } else {
        src = (const float*)d_in[0];
        ref = (const float*)d_in[1];
        aff = (const float*)d_in[2];
    }
    float* out = (float*)d_out;

    zero_kernel<<<4, 256>>>();
    knn_kernel<<<NS, 128>>>(src, NS, 0);
    knn_kernel<<<NR, 128>>>(ref, NR, 1);
    scan1_kernel<<<NS, 256>>>(aff);
    thresh_kernel<<<1, 32>>>();
    hist_low_kernel<<<NS, 256>>>(aff);   // early-exits unless unresolved
    thresh2_kernel<<<1, 32>>>();         // early-exits unless unresolved
    collect_kernel<<<NS, 256>>>(aff);    // early-exits when skip
    select_kernel<<<1, 1024>>>(out, out_size);
}

// round 13
// speedup vs baseline: 1.5367x; 1.2689x over previous
#include <cuda_runtime.h>
#include <math.h>

#define NS 2048
#define NR 2048
#define KNB 5
#define NBINS 1024
#define RFLOOR 512                 // scan1 bins only v >= 0.5 (bin 512+)
#define COLLECT_BIN 993
#define COLLECT_THR 0.9697265625f  // 993/1024, exact bin edge
#define CAP 65536
#define KEYS_CAP 4096
#define MAXIDX 104857599u
#define KNN_QPB 8
// float32 nearest to python 0.1**2
#define SIG2F 0.009999999776482582f

__device__ float    g_sd[NS*KNB];
__device__ int      g_sidx[NS*KNB];
__device__ float    g_rdT[KNB*NR];
__device__ int      g_ridxT[KNB*NR];
__device__ unsigned g_hist[NBINS];
__device__ unsigned g_ccount;
__device__ float    g_thr;
__device__ int      g_skip;
__device__ int      g_need_full;
__device__ float    g_cval[CAP];
__device__ int      g_cidx[CAP];

__global__ void zero_kernel() {
    int t = blockIdx.x * blockDim.x + threadIdx.x;
    if (t < NBINS) g_hist[t] = 0;
    if (t == 0) { g_ccount = 0; g_need_full = 0; g_skip = 0; }
}

// FMA-CONTRACTED squared distance — matches XLA's contraction (verified R11).
__device__ __forceinline__ float d2_ref(float dx, float dy, float dz) {
    return __fmaf_rn(dz, dz, __fmaf_rn(dy, dy, __fmul_rn(dx, dx)));
}

// KNN v2: warp-per-query, 8 queries/block. Per-lane top-6 by packed
// (f32 dist bits, idx) u64 key == lexicographic (dist, idx) — identical
// semantics to the R12-proven kernel — then 6-round warp shuffle-min merge.
// Ranks 1..5 of the merged top-6 = jax top_k(-cdist)[:, 1:].
__global__ __launch_bounds__(256) void knn_kernel(const float* __restrict__ pts,
                                                  int n, int mode) {
    __shared__ float sp[3 * 2048];
    int tid = threadIdx.x;
    for (int t = tid; t < 3 * n; t += 256) sp[t] = pts[t];
    __syncthreads();
    int warp = tid >> 5, lane = tid & 31;
    int q = blockIdx.x * KNN_QPB + warp;
    float px = sp[q * 3], py = sp[q * 3 + 1], pz = sp[q * 3 + 2];
    unsigned long long best[6];
#pragma unroll
    for (int t = 0; t < 6; t++) best[t] = 0xFFFFFFFFFFFFFFFFULL;
    for (int j = lane; j < n; j += 32) {
        float d2 = d2_ref(sp[j * 3] - px, sp[j * 3 + 1] - py, sp[j * 3 + 2] - pz);
        float dist = __fsqrt_rn(fmaxf(d2, 0.0f));    // jax's ranking key
        unsigned long long key =
            ((unsigned long long)__float_as_uint(dist) << 32) | (unsigned)j;
        if (key < best[5]) {
            best[5] = key;
#pragma unroll
            for (int t = 5; t > 0; t--) {
                if (best[t] < best[t - 1]) {
                    unsigned long long tmp = best[t];
                    best[t] = best[t - 1]; best[t - 1] = tmp;
                }
            }
        }
    }
    // 6-round warp merge (keys unique: idx in low bits)
    unsigned long long res[6];
    int h = 0;
#pragma unroll
    for (int t = 0; t < 6; t++) {
        unsigned long long cand = (h < 6) ? best[h] : 0xFFFFFFFFFFFFFFFFULL;
        unsigned long long mn = cand;
#pragma unroll
        for (int o = 16; o > 0; o >>= 1) {
            unsigned long long other = __shfl_xor_sync(0xFFFFFFFFu, mn, o);
            if (other < mn) mn = other;
        }
        if (cand == mn) h++;
        res[t] = mn;
    }
    if (lane >= 1 && lane <= 5) {      // drop rank 0 (self)
        unsigned long long key = res[lane];
        float dist = __uint_as_float((unsigned)(key >> 32));
        int ni = (int)(key & 0x7FFFFFFFu);
        if (ni >= n) ni = n - 1;
        int c = lane - 1;
        if (mode == 0) { g_sd[q * KNB + c] = dist; g_sidx[q * KNB + c] = ni; }
        else           { g_rdT[c * NR + q] = dist; g_ridxT[c * NR + q] = ni; }
    }
}

// SINGLE SCAN: bt >= 0.5 prefilter (exact: A2 < 1 => v < bt) gates the
// conflict-heavy LDS gather + histogram; restricted bins [0.5, 1) +
// opportunistic faithful-value collection at v >= 993/1024.
__global__ __launch_bounds__(256) void scan1_kernel(const float* __restrict__ aff) {
    __shared__ float    rows[KNB][2048];
    __shared__ unsigned hist[NBINS - RFLOOR];
    __shared__ int      s_sidx[KNB];
    int s = blockIdx.x, tid = threadIdx.x;
    if (tid < KNB) s_sidx[tid] = g_sidx[s * KNB + tid];
    for (int b = tid; b < NBINS - RFLOOR; b += 256) hist[b] = 0;
    __syncthreads();
#pragma unroll
    for (int i = 0; i < KNB; i++) {
        const float4* srcp = (const float4*)(aff + s_sidx[i] * NR);
        float4* dst = (float4*)rows[i];
        for (int c = tid; c < 512; c += 256) dst[c] = srcp[c];
    }
    float sdv[KNB];
#pragma unroll
    for (int i = 0; i < KNB; i++) sdv[i] = g_sd[s * KNB + i];
    __syncthreads();

    for (int rb = 0; rb < NR; rb += 256) {
        int r = rb + tid;
        float base = aff[s * NR + r];
        float b100 = -100.0f * base;
        float rd[KNB]; int ra[KNB];
#pragma unroll
        for (int j = 0; j < KNB; j++) {
            rd[j] = g_rdT[j * NR + r];
            ra[j] = g_ridxT[j * NR + r];
        }
#pragma unroll
        for (int i = 0; i < KNB; i++) {
#pragma unroll
            for (int j = 0; j < KNB; j++) {
                float d  = sdv[i] - rd[j];
                float dd = __fmul_rn(d, d);
                float bt = __fmaf_rn(dd, b100, base);
                if (bt >= 0.5f) {                     // exact gate for v >= 0.5
                    float v = __fmul_rn(bt, rows[i][ra[j]]);
                    if (v >= 0.5f) {
                        int bin = (int)(v * 1024.0f); // exact pow2 binning
                        if (bin > NBINS - 1) bin = NBINS - 1;
                        atomicAdd(&hist[bin - RFLOOR], 1u);
                        if (v >= COLLECT_THR) {
                            float qq  = __fdiv_rn(dd, SIG2F);
                            float tmp = __fadd_rn(1.0f, -qq);
                            tmp = fmaxf(tmp, 0.0f);
                            float vf = __fmul_rn(__fmul_rn(base, tmp), rows[i][ra[j]]);
                            unsigned pos = atomicAdd(&g_ccount, 1u);
                            if (pos < CAP) {
                                g_cval[pos] = vf;
                                g_cidx[pos] = (s * NR + r) * 25 + i * 5 + j;
                            }
                        }
                    }
                }
            }
        }
    }
    __syncthreads();
    for (int b = tid; b < NBINS - RFLOOR; b += 256) {
        unsigned c = hist[b];
        if (c) atomicAdd(&g_hist[RFLOOR + b], c);
    }
}

// Threshold from the restricted histogram; full-histogram fallback when the
// 512th value can't be resolved strictly above the floor.
__global__ void thresh_kernel() {
    if (threadIdx.x == 0 && blockIdx.x == 0) {
        unsigned suf = 0; int bstar = -1;
        for (int b = NBINS - 1; b >= RFLOOR; b--) {
            suf += g_hist[b];
            if (suf >= 512) { bstar = b; break; }
        }
        if (bstar <= RFLOOR) {
            g_need_full = 1;
            g_skip = 0;
            return;
        }
        int ba = bstar - 1;             // one-bin slack (>= RFLOOR, counted)
        unsigned cnt = suf + g_hist[ba];
        while (cnt > CAP && ba < NBINS - 1) {
            cnt -= g_hist[ba];
            ba++;
        }
        g_thr = (float)ba * (1.0f / 1024.0f);
        int skip = (ba >= COLLECT_BIN && g_ccount <= CAP) ? 1 : 0;
        g_skip = skip;
        if (!skip) g_ccount = 0;
    }
}

// Conditional: fill bins [0, RFLOOR) — runs only when thresh couldn't resolve.
__global__ __launch_bounds__(256) void hist_low_kernel(const float* __restrict__ aff) {
    if (!g_need_full) return;
    __shared__ float    rows[KNB][2048];
    __shared__ unsigned hist[RFLOOR];
    __shared__ int      s_sidx[KNB];
    int s = blockIdx.x, tid = threadIdx.x;
    if (tid < KNB) s_sidx[tid] = g_sidx[s * KNB + tid];
    for (int b = tid; b < RFLOOR; b += 256) hist[b] = 0;
    __syncthreads();
#pragma unroll
    for (int i = 0; i < KNB; i++) {
        const float4* srcp = (const float4*)(aff + s_sidx[i] * NR);
        float4* dst = (float4*)rows[i];
        for (int c = tid; c < 512; c += 256) dst[c] = srcp[c];
    }
    float sdv[KNB];
#pragma unroll
    for (int i = 0; i < KNB; i++) sdv[i] = g_sd[s * KNB + i];
    __syncthreads();
    for (int rb = 0; rb < NR; rb += 256) {
        int r = rb + tid;
        float base = aff[s * NR + r];
        float b100 = -100.0f * base;
        float rd[KNB]; int ra[KNB];
#pragma unroll
        for (int j = 0; j < KNB; j++) {
            rd[j] = g_rdT[j * NR + r];
            ra[j] = g_ridxT[j * NR + r];
        }
#pragma unroll
        for (int i = 0; i < KNB; i++) {
#pragma unroll
            for (int j = 0; j < KNB; j++) {
                float d  = sdv[i] - rd[j];
                float bt = __fmaf_rn(__fmul_rn(d, d), b100, base);
                float v  = __fmul_rn(bt, rows[i][ra[j]]);
                if (v > 0.0f && v < 0.5f) {
                    int bin = (int)(v * 1024.0f);
                    if (bin < RFLOOR) atomicAdd(&hist[bin], 1u);
                }
            }
        }
    }
    __syncthreads();
    for (int b = tid; b < RFLOOR; b += 256) {
        unsigned c = hist[b];
        if (c) atomicAdd(&g_hist[b], c);
    }
}

// Conditional: re-threshold over the complete histogram.
__global__ void thresh2_kernel() {
    if (threadIdx.x == 0 && blockIdx.x == 0) {
        if (!g_need_full) return;
        unsigned suf = 0; int bstar = -1;
        for (int b = NBINS - 1; b >= 0; b--) {
            suf += g_hist[b];
            if (suf >= 512) { bstar = b; break; }
        }
        if (bstar < 0) bstar = 0;
        int ba = bstar > 0 ? bstar - 1 : 0;
        unsigned cnt = suf + ((ba < bstar) ? g_hist[ba] : 0u);
        while (cnt > CAP && ba < NBINS - 1) {
            cnt -= g_hist[ba];
            ba++;
        }
        g_thr = (float)ba * (1.0f / 1024.0f);
        if (g_thr < 1e-30f) g_thr = 1e-30f;
        g_skip = 0;
        g_ccount = 0;
    }
}

// Fallback collect (usually skipped): admit hot v >= thr, store faithful value.
__global__ __launch_bounds__(256) void collect_kernel(const float* __restrict__ aff) {
    if (g_skip) return;
    __shared__ float rows[KNB][2048];
    __shared__ int   s_sidx[KNB];
    int s = blockIdx.x, tid = threadIdx.x;
    if (tid < KNB) s_sidx[tid] = g_sidx[s * KNB + tid];
    __syncthreads();
#pragma unroll
    for (int i = 0; i < KNB; i++) {
        const float4* srcp = (const float4*)(aff + s_sidx[i] * NR);
        float4* dst = (float4*)rows[i];
        for (int c = tid; c < 512; c += 256) dst[c] = srcp[c];
    }
    float thr = g_thr;
    float sdv[KNB];
#pragma unroll
    for (int i = 0; i < KNB; i++) sdv[i] = g_sd[s * KNB + i];
    __syncthreads();
    for (int rb = 0; rb < NR; rb += 256) {
        int r = rb + tid;
        float base = aff[s * NR + r];
        float b100 = -100.0f * base;
        float rd[KNB]; int ra[KNB];
#pragma unroll
        for (int j = 0; j < KNB; j++) {
            rd[j] = g_rdT[j * NR + r];
            ra[j] = g_ridxT[j * NR + r];
        }
#pragma unroll
        for (int i = 0; i < KNB; i++) {
#pragma unroll
            for (int j = 0; j < KNB; j++) {
                float d  = sdv[i] - rd[j];
                float dd = __fmul_rn(d, d);
                float bt = __fmaf_rn(dd, b100, base);
                if (bt >= thr) {
                    float v = __fmul_rn(bt, rows[i][ra[j]]);
                    if (v >= thr && v > 0.0f) {
                        float qq  = __fdiv_rn(dd, SIG2F);
                        float tmp = __fadd_rn(1.0f, -qq);
                        tmp = fmaxf(tmp, 0.0f);
                        float vf = __fmul_rn(__fmul_rn(base, tmp), rows[i][ra[j]]);
                        unsigned pos = atomicAdd(&g_ccount, 1u);
                        if (pos < CAP) {
                            g_cval[pos] = vf;
                            g_cidx[pos] = (s * NR + r) * 25 + i * 5 + j;
                        }
                    }
                }
            }
        }
    }
}

// Select (unchanged, proven): refine -> bitonic -> emit f32 indices.
__global__ __launch_bounds__(1024) void select_kernel(float* __restrict__ out,
                                                      int out_size) {
    __shared__ unsigned long long keys[KEYS_CAP];
    __shared__ unsigned h2[1024];
    __shared__ unsigned m2;
    __shared__ float sh_thr2;
    int tid = threadIdx.x;
    unsigned M = g_ccount; if (M > CAP) M = CAP;
    float thr = g_thr;
    h2[tid] = 0;
    if (tid == 0) { m2 = 0; sh_thr2 = -1.0f; }
    __syncthreads();
    if (M > KEYS_CAP) {
        float binw2 = (1.0f - thr) * (1.0f / 1024.0f);
        if (binw2 <= 0.0f) binw2 = 1e-9f;
        for (unsigned c = tid; c < M; c += 1024) {
            float v = g_cval[c];
            int b = (int)((v - thr) / binw2);
            if (b < 0) b = 0;
            if (b > 1023) b = 1023;
            atomicAdd(&h2[b], 1u);
        }
        __syncthreads();
        if (tid == 0) {
            unsigned suf = 0; int b2 = 0;
            for (int b = 1023; b >= 0; b--) {
                suf += h2[b];
                if (suf >= 512) { b2 = b; break; }
            }
            int ba = b2;
            unsigned cnt = suf;
            if (ba > 0 && cnt + h2[ba - 1] <= (unsigned)KEYS_CAP) {
                ba--; cnt += h2[ba];
            }
            while (cnt > (unsigned)KEYS_CAP && ba < 1023) {
                cnt -= h2[ba]; ba++;
            }
            sh_thr2 = thr + (float)ba * binw2;
            if (sh_thr2 < thr) sh_thr2 = thr;
        }
        __syncthreads();
    }
    float thr2 = sh_thr2;   // -1 => keep all
    for (unsigned c = tid; c < M; c += 1024) {
        float v = g_cval[c];
        if (v >= thr2) {
            unsigned p = atomicAdd(&m2, 1u);
            if (p < KEYS_CAP) {
                unsigned idx = (unsigned)g_cidx[c];
                if (idx > MAXIDX) idx = MAXIDX;
                keys[p] = ((unsigned long long)__float_as_uint(v) << 32)
                        | (unsigned long long)(0xFFFFFFFFu - idx);
            }
        }
    }
    __syncthreads();
    unsigned M2 = m2; if (M2 > KEYS_CAP) M2 = KEYS_CAP;
    for (unsigned e = M2 + tid; e < KEYS_CAP; e += 1024) keys[e] = 0ull;
    __syncthreads();
    for (unsigned k = 2; k <= KEYS_CAP; k <<= 1) {
        for (unsigned jj = k >> 1; jj > 0; jj >>= 1) {
            for (unsigned e = tid; e < KEYS_CAP; e += 1024) {
                unsigned partner = e ^ jj;
                if (partner > e) {
                    unsigned long long A = keys[e], B = keys[partner];
                    bool desc = ((e & k) == 0);
                    if (desc ? (A < B) : (A > B)) { keys[e] = B; keys[partner] = A; }
                }
            }
            __syncthreads();
        }
    }
    if (tid < 512) {
        unsigned long long key = keys[tid];
        unsigned idx = 0xFFFFFFFFu - (unsigned)(key & 0xFFFFFFFFull);
        if (idx > MAXIDX) idx = MAXIDX;
        int s = (int)(idx / 51200u);  int rem = (int)(idx - (unsigned)s * 51200u);
        int r = rem / 25;             int ij  = rem - r * 25;
        int i = ij / 5;               int j   = ij - i * 5;
        if (s > NS - 1) s = NS - 1;
        if (r > NR - 1) r = NR - 1;
        if (tid < out_size)        out[tid]        = (float)s;
        if (512 + tid < out_size)  out[512 + tid]  = (float)r;
        if (1024 + tid < out_size) out[1024 + tid] = (float)g_sidx[s * KNB + i];
        if (1536 + tid < out_size) out[1536 + tid] = (float)g_ridxT[j * NR + r];
    }
}

extern "C" void kernel_launch(void* const* d_in, const int* in_sizes, int n_in,
                              void* d_out, int out_size) {
    const float *src, *ref, *aff;
    if (in_sizes[0] >= (1 << 20)) {
        aff = (const float*)d_in[0];
        ref = (const float*)d_in[1];
        src = (const float*)d_in[2];
    } else {
        src = (const float*)d_in[0];
        ref = (const float*)d_in[1];
        aff = (const float*)d_in[2];
    }
    float* out = (float*)d_out;

    zero_kernel<<<4, 256>>>();
    knn_kernel<<<NS / KNN_QPB, 256>>>(src, NS, 0);
    knn_kernel<<<NR / KNN_QPB, 256>>>(ref, NR, 1);
    scan1_kernel<<<NS, 256>>>(aff);
    thresh_kernel<<<1, 32>>>();
    hist_low_kernel<<<NS, 256>>>(aff);   // early-exits unless unresolved
    thresh2_kernel<<<1, 32>>>();         // early-exits unless unresolved
    collect_kernel<<<NS, 256>>>(aff);    // early-exits when skip
    select_kernel<<<1, 1024>>>(out, out_size);
}

// round 14
// speedup vs baseline: 2.0756x; 1.3507x over previous
#include <cuda_runtime.h>
#include <math.h>

#define NS 2048
#define NR 2048
#define KNB 5
#define NBINS 1024
#define RFLOOR 960                 // scan1 bins only v >= 0.9375 (bin 960+)
#define GATEF 0.9375f              // 960/1024, exact bin edge
#define COLLECT_BIN 993
#define COLLECT_THR 0.9697265625f  // 993/1024, exact bin edge
#define CAP 65536
#define KEYS_CAP 4096
#define MAXIDX 104857599u
#define KNN_QPB 8
// float32 nearest to python 0.1**2
#define SIG2F 0.009999999776482582f

__device__ float    g_sd[NS*KNB];
__device__ int      g_sidx[NS*KNB];
__device__ float    g_rdT[KNB*NR];
__device__ int      g_ridxT[KNB*NR];
__device__ unsigned g_hist[NBINS];
__device__ unsigned g_ccount;
__device__ float    g_thr;
__device__ int      g_skip;
__device__ int      g_need_full;
__device__ float    g_cval[CAP];
__device__ int      g_cidx[CAP];

__global__ void zero_kernel() {
    int t = blockIdx.x * blockDim.x + threadIdx.x;
    if (t < NBINS) g_hist[t] = 0;
    if (t == 0) { g_ccount = 0; g_need_full = 0; g_skip = 0; }
}

// FMA-CONTRACTED squared distance — matches XLA's contraction (verified R11).
__device__ __forceinline__ float d2_ref(float dx, float dy, float dz) {
    return __fmaf_rn(dz, dz, __fmaf_rn(dy, dy, __fmul_rn(dx, dx)));
}

// KNN (proven R13): warp-per-query, packed (dist, idx) keys, warp merge.
__global__ __launch_bounds__(256) void knn_kernel(const float* __restrict__ pts,
                                                  int n, int mode) {
    __shared__ float sp[3 * 2048];
    int tid = threadIdx.x;
    for (int t = tid; t < 3 * n; t += 256) sp[t] = pts[t];
    __syncthreads();
    int warp = tid >> 5, lane = tid & 31;
    int q = blockIdx.x * KNN_QPB + warp;
    float px = sp[q * 3], py = sp[q * 3 + 1], pz = sp[q * 3 + 2];
    unsigned long long best[6];
#pragma unroll
    for (int t = 0; t < 6; t++) best[t] = 0xFFFFFFFFFFFFFFFFULL;
    for (int j = lane; j < n; j += 32) {
        float d2 = d2_ref(sp[j * 3] - px, sp[j * 3 + 1] - py, sp[j * 3 + 2] - pz);
        float dist = __fsqrt_rn(fmaxf(d2, 0.0f));    // jax's ranking key
        unsigned long long key =
            ((unsigned long long)__float_as_uint(dist) << 32) | (unsigned)j;
        if (key < best[5]) {
            best[5] = key;
#pragma unroll
            for (int t = 5; t > 0; t--) {
                if (best[t] < best[t - 1]) {
                    unsigned long long tmp = best[t];
                    best[t] = best[t - 1]; best[t - 1] = tmp;
                }
            }
        }
    }
    unsigned long long res[6];
    int h = 0;
#pragma unroll
    for (int t = 0; t < 6; t++) {
        unsigned long long cand = (h < 6) ? best[h] : 0xFFFFFFFFFFFFFFFFULL;
        unsigned long long mn = cand;
#pragma unroll
        for (int o = 16; o > 0; o >>= 1) {
            unsigned long long other = __shfl_xor_sync(0xFFFFFFFFu, mn, o);
            if (other < mn) mn = other;
        }
        if (cand == mn) h++;
        res[t] = mn;
    }
    if (lane >= 1 && lane <= 5) {      // drop rank 0 (self)
        unsigned long long key = res[lane];
        float dist = __uint_as_float((unsigned)(key >> 32));
        int ni = (int)(key & 0x7FFFFFFFu);
        if (ni >= n) ni = n - 1;
        int c = lane - 1;
        if (mode == 0) { g_sd[q * KNB + c] = dist; g_sidx[q * KNB + c] = ni; }
        else           { g_rdT[c * NR + q] = dist; g_ridxT[c * NR + q] = ni; }
    }
}

// SCAN v3: compact r's with base >= 0.9375 (exact gate: temp<=1, A2<1 =>
// v >= G requires base >= G), then UNCONDITIONAL 25-combo body per survivor
// (R13 lesson: no per-combo branches). Histogram bins [960,1024) only;
// collect faithful values at v >= 993/1024.
__global__ __launch_bounds__(256) void scan1_kernel(const float* __restrict__ aff) {
    __shared__ float    rows[KNB][2048];
    __shared__ int      rlist[2048];
    __shared__ float    rbase[2048];
    __shared__ unsigned hist[NBINS - RFLOOR];
    __shared__ int      s_sidx[KNB];
    __shared__ unsigned rcnt;
    int s = blockIdx.x, tid = threadIdx.x;
    if (tid < KNB) s_sidx[tid] = g_sidx[s * KNB + tid];
    if (tid == 0) rcnt = 0;
    for (int b = tid; b < NBINS - RFLOOR; b += 256) hist[b] = 0;
    __syncthreads();
#pragma unroll
    for (int i = 0; i < KNB; i++) {
        const float4* srcp = (const float4*)(aff + s_sidx[i] * NR);
        float4* dst = (float4*)rows[i];
        for (int c = tid; c < 512; c += 256) dst[c] = srcp[c];
    }
    // Phase A: compact candidate r's (coalesced base sweep)
    for (int r = tid; r < NR; r += 256) {
        float base = aff[s * NR + r];
        if (base >= GATEF) {
            unsigned p = atomicAdd(&rcnt, 1u);
            rlist[p] = r; rbase[p] = base;
        }
    }
    float sdv[KNB];
#pragma unroll
    for (int i = 0; i < KNB; i++) sdv[i] = g_sd[s * KNB + i];
    __syncthreads();
    int cnt = rcnt;
    // Phase B: thread-per-survivor, 25 unconditional combos
    for (int k = tid; k < cnt; k += 256) {
        int r = rlist[k];
        float base = rbase[k];
        float b100 = -100.0f * base;
        float rd[KNB]; int ra[KNB];
#pragma unroll
        for (int j = 0; j < KNB; j++) {
            rd[j] = g_rdT[j * NR + r];
            ra[j] = g_ridxT[j * NR + r];
        }
#pragma unroll
        for (int i = 0; i < KNB; i++) {
#pragma unroll
            for (int j = 0; j < KNB; j++) {
                float d  = sdv[i] - rd[j];
                float dd = __fmul_rn(d, d);
                float bt = __fmaf_rn(dd, b100, base);
                float v  = __fmul_rn(bt, rows[i][ra[j]]);
                if (v >= GATEF) {
                    int bin = (int)(v * 1024.0f);     // exact pow2 binning
                    if (bin > NBINS - 1) bin = NBINS - 1;
                    atomicAdd(&hist[bin - RFLOOR], 1u);
                    if (v >= COLLECT_THR) {
                        float qq  = __fdiv_rn(dd, SIG2F);
                        float tmp = __fadd_rn(1.0f, -qq);
                        tmp = fmaxf(tmp, 0.0f);
                        float vf = __fmul_rn(__fmul_rn(base, tmp), rows[i][ra[j]]);
                        unsigned pos = atomicAdd(&g_ccount, 1u);
                        if (pos < CAP) {
                            g_cval[pos] = vf;
                            g_cidx[pos] = (s * NR + r) * 25 + i * 5 + j;
                        }
                    }
                }
            }
        }
    }
    __syncthreads();
    for (int b = tid; b < NBINS - RFLOOR; b += 256) {
        unsigned c = hist[b];
        if (c) atomicAdd(&g_hist[RFLOOR + b], c);
    }
}

// Threshold from the restricted histogram; full-histogram fallback when the
// 512th value can't be resolved strictly above the floor.
__global__ void thresh_kernel() {
    if (threadIdx.x == 0 && blockIdx.x == 0) {
        unsigned suf = 0; int bstar = -1;
        for (int b = NBINS - 1; b >= RFLOOR; b--) {
            suf += g_hist[b];
            if (suf >= 512) { bstar = b; break; }
        }
        if (bstar <= RFLOOR) {
            g_need_full = 1;
            g_skip = 0;
            return;
        }
        int ba = bstar - 1;             // one-bin slack (>= RFLOOR, counted)
        unsigned cnt = suf + g_hist[ba];
        while (cnt > CAP && ba < NBINS - 1) {
            cnt -= g_hist[ba];
            ba++;
        }
        g_thr = (float)ba * (1.0f / 1024.0f);
        int skip = (ba >= COLLECT_BIN && g_ccount <= CAP) ? 1 : 0;
        g_skip = skip;
        if (!skip) g_ccount = 0;
    }
}

// Conditional full low-bin histogram [0, RFLOOR) — only when unresolved.
__global__ __launch_bounds__(256) void hist_low_kernel(const float* __restrict__ aff) {
    if (!g_need_full) return;
    __shared__ float    rows[KNB][2048];
    __shared__ unsigned hist[RFLOOR];
    __shared__ int      s_sidx[KNB];
    int s = blockIdx.x, tid = threadIdx.x;
    if (tid < KNB) s_sidx[tid] = g_sidx[s * KNB + tid];
    for (int b = tid; b < RFLOOR; b += 256) hist[b] = 0;
    __syncthreads();
#pragma unroll
    for (int i = 0; i < KNB; i++) {
        const float4* srcp = (const float4*)(aff + s_sidx[i] * NR);
        float4* dst = (float4*)rows[i];
        for (int c = tid; c < 512; c += 256) dst[c] = srcp[c];
    }
    float sdv[KNB];
#pragma unroll
    for (int i = 0; i < KNB; i++) sdv[i] = g_sd[s * KNB + i];
    __syncthreads();
    for (int rb = 0; rb < NR; rb += 256) {
        int r = rb + tid;
        float base = aff[s * NR + r];
        float b100 = -100.0f * base;
        float rd[KNB]; int ra[KNB];
#pragma unroll
        for (int j = 0; j < KNB; j++) {
            rd[j] = g_rdT[j * NR + r];
            ra[j] = g_ridxT[j * NR + r];
        }
#pragma unroll
        for (int i = 0; i < KNB; i++) {
#pragma unroll
            for (int j = 0; j < KNB; j++) {
                float d  = sdv[i] - rd[j];
                float bt = __fmaf_rn(__fmul_rn(d, d), b100, base);
                float v  = __fmul_rn(bt, rows[i][ra[j]]);
                if (v > 0.0f && v < GATEF) {
                    int bin = (int)(v * 1024.0f);
                    if (bin < RFLOOR) atomicAdd(&hist[bin], 1u);
                }
            }
        }
    }
    __syncthreads();
    for (int b = tid; b < RFLOOR; b += 256) {
        unsigned c = hist[b];
        if (c) atomicAdd(&g_hist[b], c);
    }
}

// Conditional: re-threshold over the complete histogram.
__global__ void thresh2_kernel() {
    if (threadIdx.x == 0 && blockIdx.x == 0) {
        if (!g_need_full) return;
        unsigned suf = 0; int bstar = -1;
        for (int b = NBINS - 1; b >= 0; b--) {
            suf += g_hist[b];
            if (suf >= 512) { bstar = b; break; }
        }
        if (bstar < 0) bstar = 0;
        int ba = bstar > 0 ? bstar - 1 : 0;
        unsigned cnt = suf + ((ba < bstar) ? g_hist[ba] : 0u);
        while (cnt > CAP && ba < NBINS - 1) {
            cnt -= g_hist[ba];
            ba++;
        }
        g_thr = (float)ba * (1.0f / 1024.0f);
        if (g_thr < 1e-30f) g_thr = 1e-30f;
        g_skip = 0;
        g_ccount = 0;
    }
}

// Fallback collect (usually skipped): admit hot v >= thr, store faithful value.
__global__ __launch_bounds__(256) void collect_kernel(const float* __restrict__ aff) {
    if (g_skip) return;
    __shared__ float rows[KNB][2048];
    __shared__ int   s_sidx[KNB];
    int s = blockIdx.x, tid = threadIdx.x;
    if (tid < KNB) s_sidx[tid] = g_sidx[s * KNB + tid];
    __syncthreads();
#pragma unroll
    for (int i = 0; i < KNB; i++) {
        const float4* srcp = (const float4*)(aff + s_sidx[i] * NR);
        float4* dst = (float4*)rows[i];
        for (int c = tid; c < 512; c += 256) dst[c] = srcp[c];
    }
    float thr = g_thr;
    float sdv[KNB];
#pragma unroll
    for (int i = 0; i < KNB; i++) sdv[i] = g_sd[s * KNB + i];
    __syncthreads();
    for (int rb = 0; rb < NR; rb += 256) {
        int r = rb + tid;
        float base = aff[s * NR + r];
        float b100 = -100.0f * base;
        float rd[KNB]; int ra[KNB];
#pragma unroll
        for (int j = 0; j < KNB; j++) {
            rd[j] = g_rdT[j * NR + r];
            ra[j] = g_ridxT[j * NR + r];
        }
#pragma unroll
        for (int i = 0; i < KNB; i++) {
#pragma unroll
            for (int j = 0; j < KNB; j++) {
                float d  = sdv[i] - rd[j];
                float dd = __fmul_rn(d, d);
                float bt = __fmaf_rn(dd, b100, base);
                if (bt >= thr) {
                    float v = __fmul_rn(bt, rows[i][ra[j]]);
                    if (v >= thr && v > 0.0f) {
                        float qq  = __fdiv_rn(dd, SIG2F);
                        float tmp = __fadd_rn(1.0f, -qq);
                        tmp = fmaxf(tmp, 0.0f);
                        float vf = __fmul_rn(__fmul_rn(base, tmp), rows[i][ra[j]]);
                        unsigned pos = atomicAdd(&g_ccount, 1u);
                        if (pos < CAP) {
                            g_cval[pos] = vf;
                            g_cidx[pos] = (s * NR + r) * 25 + i * 5 + j;
                        }
                    }
                }
            }
        }
    }
}

// Select (unchanged, proven): refine -> bitonic -> emit f32 indices.
__global__ __launch_bounds__(1024) void select_kernel(float* __restrict__ out,
                                                      int out_size) {
    __shared__ unsigned long long keys[KEYS_CAP];
    __shared__ unsigned h2[1024];
    __shared__ unsigned m2;
    __shared__ float sh_thr2;
    int tid = threadIdx.x;
    unsigned M = g_ccount; if (M > CAP) M = CAP;
    float thr = g_thr;
    h2[tid] = 0;
    if (tid == 0) { m2 = 0; sh_thr2 = -1.0f; }
    __syncthreads();
    if (M > KEYS_CAP) {
        float binw2 = (1.0f - thr) * (1.0f / 1024.0f);
        if (binw2 <= 0.0f) binw2 = 1e-9f;
        for (unsigned c = tid; c < M; c += 1024) {
            float v = g_cval[c];
            int b = (int)((v - thr) / binw2);
            if (b < 0) b = 0;
            if (b > 1023) b = 1023;
            atomicAdd(&h2[b], 1u);
        }
        __syncthreads();
        if (tid == 0) {
            unsigned suf = 0; int b2 = 0;
            for (int b = 1023; b >= 0; b--) {
                suf += h2[b];
                if (suf >= 512) { b2 = b; break; }
            }
            int ba = b2;
            unsigned cnt = suf;
            if (ba > 0 && cnt + h2[ba - 1] <= (unsigned)KEYS_CAP) {
                ba--; cnt += h2[ba];
            }
            while (cnt > (unsigned)KEYS_CAP && ba < 1023) {
                cnt -= h2[ba]; ba++;
            }
            sh_thr2 = thr + (float)ba * binw2;
            if (sh_thr2 < thr) sh_thr2 = thr;
        }
        __syncthreads();
    }
    float thr2 = sh_thr2;   // -1 => keep all
    for (unsigned c = tid; c < M; c += 1024) {
        float v = g_cval[c];
        if (v >= thr2) {
            unsigned p = atomicAdd(&m2, 1u);
            if (p < KEYS_CAP) {
                unsigned idx = (unsigned)g_cidx[c];
                if (idx > MAXIDX) idx = MAXIDX;
                keys[p] = ((unsigned long long)__float_as_uint(v) << 32)
                        | (unsigned long long)(0xFFFFFFFFu - idx);
            }
        }
    }
    __syncthreads();
    unsigned M2 = m2; if (M2 > KEYS_CAP) M2 = KEYS_CAP;
    for (unsigned e = M2 + tid; e < KEYS_CAP; e += 1024) keys[e] = 0ull;
    __syncthreads();
    for (unsigned k = 2; k <= KEYS_CAP; k <<= 1) {
        for (unsigned jj = k >> 1; jj > 0; jj >>= 1) {
            for (unsigned e = tid; e < KEYS_CAP; e += 1024) {
                unsigned partner = e ^ jj;
                if (partner > e) {
                    unsigned long long A = keys[e], B = keys[partner];
                    bool desc = ((e & k) == 0);
                    if (desc ? (A < B) : (A > B)) { keys[e] = B; keys[partner] = A; }
                }
            }
            __syncthreads();
        }
    }
    if (tid < 512) {
        unsigned long long key = keys[tid];
        unsigned idx = 0xFFFFFFFFu - (unsigned)(key & 0xFFFFFFFFull);
        if (idx > MAXIDX) idx = MAXIDX;
        int s = (int)(idx / 51200u);  int rem = (int)(idx - (unsigned)s * 51200u);
        int r = rem / 25;             int ij  = rem - r * 25;
        int i = ij / 5;               int j   = ij - i * 5;
        if (s > NS - 1) s = NS - 1;
        if (r > NR - 1) r = NR - 1;
        if (tid < out_size)        out[tid]        = (float)s;
        if (512 + tid < out_size)  out[512 + tid]  = (float)r;
        if (1024 + tid < out_size) out[1024 + tid] = (float)g_sidx[s * KNB + i];
        if (1536 + tid < out_size) out[1536 + tid] = (float)g_ridxT[j * NR + r];
    }
}

extern "C" void kernel_launch(void* const* d_in, const int* in_sizes, int n_in,
                              void* d_out, int out_size) {
    const float *src, *ref, *aff;
    if (in_sizes[0] >= (1 << 20)) {
        aff = (const float*)d_in[0];
        ref = (const float*)d_in[1];
        src = (const float*)d_in[2];
    } else {
        src = (const float*)d_in[0];
        ref = (const float*)d_in[1];
        aff = (const float*)d_in[2];
    }
    float* out = (float*)d_out;

    zero_kernel<<<4, 256>>>();
    knn_kernel<<<NS / KNN_QPB, 256>>>(src, NS, 0);
    knn_kernel<<<NR / KNN_QPB, 256>>>(ref, NR, 1);
    scan1_kernel<<<NS, 256>>>(aff);
    thresh_kernel<<<1, 32>>>();
    hist_low_kernel<<<NS, 256>>>(aff);   // early-exits unless unresolved
    thresh2_kernel<<<1, 32>>>();         // early-exits unless unresolved
    collect_kernel<<<NS, 256>>>(aff);    // early-exits when skip
    select_kernel<<<1, 1024>>>(out, out_size);
}

// round 15
// speedup vs baseline: 2.3263x; 1.1208x over previous
#include <cuda_runtime.h>
#include <math.h>

#define NS 2048
#define NR 2048
#define KNB 5
#define NBINS 1024
#define RFLOOR 960                 // scan1 bins only v >= 0.9375 (bin 960+)
#define GATEF 0.9375f              // 960/1024, exact bin edge
#define COLLECT_BIN 993
#define COLLECT_THR 0.9697265625f  // 993/1024, exact bin edge
#define CAP 65536
#define KEYS_CAP 4096
#define MAXIDX 104857599u
#define KNN_QPB 8
// float32 nearest to python 0.1**2
#define SIG2F 0.009999999776482582f

__device__ float    g_sd[NS*KNB];
__device__ int      g_sidx[NS*KNB];
__device__ float    g_rdT[KNB*NR];
__device__ int      g_ridxT[KNB*NR];
__device__ unsigned g_hist[NBINS];
__device__ unsigned g_ccount;
__device__ float    g_thr;
__device__ int      g_skip;
__device__ int      g_need_full;
__device__ float    g_cval[CAP];
__device__ int      g_cidx[CAP];

__global__ void zero_kernel() {
    int t = blockIdx.x * blockDim.x + threadIdx.x;
    if (t < NBINS) g_hist[t] = 0;
    if (t == 0) { g_ccount = 0; g_need_full = 0; g_skip = 0; }
}

// FMA-CONTRACTED squared distance — matches XLA's contraction (verified R11).
__device__ __forceinline__ float d2_ref(float dx, float dy, float dz) {
    return __fmaf_rn(dz, dz, __fmaf_rn(dy, dy, __fmul_rn(dx, dx)));
}

// KNN (proven R13 core), both point sets in ONE launch:
// blocks [0, 256) -> src (mode 0), blocks [256, 512) -> ref (mode 1).
__global__ __launch_bounds__(256) void knn_kernel(const float* __restrict__ src,
                                                  const float* __restrict__ ref) {
    __shared__ float sp[3 * 2048];
    int tid = threadIdx.x;
    int mode = (blockIdx.x >= (NS / KNN_QPB)) ? 1 : 0;
    const float* pts = mode ? ref : src;
    int bq = mode ? (blockIdx.x - NS / KNN_QPB) : blockIdx.x;
    const int n = 2048;
    for (int t = tid; t < 3 * n; t += 256) sp[t] = pts[t];
    __syncthreads();
    int warp = tid >> 5, lane = tid & 31;
    int q = bq * KNN_QPB + warp;
    float px = sp[q * 3], py = sp[q * 3 + 1], pz = sp[q * 3 + 2];
    unsigned long long best[6];
#pragma unroll
    for (int t = 0; t < 6; t++) best[t] = 0xFFFFFFFFFFFFFFFFULL;
    for (int j = lane; j < n; j += 32) {
        float d2 = d2_ref(sp[j * 3] - px, sp[j * 3 + 1] - py, sp[j * 3 + 2] - pz);
        float dist = __fsqrt_rn(fmaxf(d2, 0.0f));    // jax's ranking key
        unsigned long long key =
            ((unsigned long long)__float_as_uint(dist) << 32) | (unsigned)j;
        if (key < best[5]) {
            best[5] = key;
#pragma unroll
            for (int t = 5; t > 0; t--) {
                if (best[t] < best[t - 1]) {
                    unsigned long long tmp = best[t];
                    best[t] = best[t - 1]; best[t - 1] = tmp;
                }
            }
        }
    }
    unsigned long long res[6];
    int h = 0;
#pragma unroll
    for (int t = 0; t < 6; t++) {
        unsigned long long cand = (h < 6) ? best[h] : 0xFFFFFFFFFFFFFFFFULL;
        unsigned long long mn = cand;
#pragma unroll
        for (int o = 16; o > 0; o >>= 1) {
            unsigned long long other = __shfl_xor_sync(0xFFFFFFFFu, mn, o);
            if (other < mn) mn = other;
        }
        if (cand == mn) h++;
        res[t] = mn;
    }
    if (lane >= 1 && lane <= 5) {      // drop rank 0 (self)
        unsigned long long key = res[lane];
        float dist = __uint_as_float((unsigned)(key >> 32));
        int ni = (int)(key & 0x7FFFFFFFu);
        if (ni >= n) ni = n - 1;
        int c = lane - 1;
        if (mode == 0) { g_sd[q * KNB + c] = dist; g_sidx[q * KNB + c] = ni; }
        else           { g_rdT[c * NR + q] = dist; g_ridxT[c * NR + q] = ni; }
    }
}

// SCAN v4: no row staging. Phase A compacts r's with base >= 0.9375 (exact
// gate); Phase B gathers A2 directly from L2 (aff is L2-resident, 25
// unconditional gathers per survivor -> MLP hides latency). smem ~16.5KB.
__global__ __launch_bounds__(256) void scan1_kernel(const float* __restrict__ aff) {
    __shared__ int      rlist[2048];
    __shared__ float    rbase[2048];
    __shared__ unsigned hist[NBINS - RFLOOR];
    __shared__ int      s_sidx[KNB];
    __shared__ unsigned rcnt;
    int s = blockIdx.x, tid = threadIdx.x;
    if (tid < KNB) s_sidx[tid] = g_sidx[s * KNB + tid];
    if (tid == 0) rcnt = 0;
    for (int b = tid; b < NBINS - RFLOOR; b += 256) hist[b] = 0;
    __syncthreads();
    // Phase A: coalesced float4 base sweep + compaction
    const float4* bp = (const float4*)(aff + s * NR);
    for (int c = tid; c < 512; c += 256) {
        float4 b4 = bp[c];
        if (b4.x >= GATEF) { unsigned p = atomicAdd(&rcnt, 1u); rlist[p] = c*4+0; rbase[p] = b4.x; }
        if (b4.y >= GATEF) { unsigned p = atomicAdd(&rcnt, 1u); rlist[p] = c*4+1; rbase[p] = b4.y; }
        if (b4.z >= GATEF) { unsigned p = atomicAdd(&rcnt, 1u); rlist[p] = c*4+2; rbase[p] = b4.z; }
        if (b4.w >= GATEF) { unsigned p = atomicAdd(&rcnt, 1u); rlist[p] = c*4+3; rbase[p] = b4.w; }
    }
    float sdv[KNB];
#pragma unroll
    for (int i = 0; i < KNB; i++) sdv[i] = g_sd[s * KNB + i];
    int rowb[KNB];
#pragma unroll
    for (int i = 0; i < KNB; i++) rowb[i] = s_sidx[i] * NR;   // s_sidx set pre-sync? guard:
    __syncthreads();
#pragma unroll
    for (int i = 0; i < KNB; i++) rowb[i] = s_sidx[i] * NR;   // re-read post-sync (cheap)
    int cnt = rcnt;
    // Phase B: thread-per-survivor, 25 unconditional combos, direct L2 gathers
    for (int k = tid; k < cnt; k += 256) {
        int r = rlist[k];
        float base = rbase[k];
        float b100 = -100.0f * base;
        float rd[KNB]; int ra[KNB];
#pragma unroll
        for (int j = 0; j < KNB; j++) {
            rd[j] = g_rdT[j * NR + r];
            ra[j] = g_ridxT[j * NR + r];
        }
        float a2v[KNB][KNB];
#pragma unroll
        for (int i = 0; i < KNB; i++)
#pragma unroll
            for (int j = 0; j < KNB; j++)
                a2v[i][j] = __ldg(&aff[rowb[i] + ra[j]]);
#pragma unroll
        for (int i = 0; i < KNB; i++) {
#pragma unroll
            for (int j = 0; j < KNB; j++) {
                float d  = sdv[i] - rd[j];
                float dd = __fmul_rn(d, d);
                float bt = __fmaf_rn(dd, b100, base);
                float v  = __fmul_rn(bt, a2v[i][j]);
                if (v >= GATEF) {
                    int bin = (int)(v * 1024.0f);     // exact pow2 binning
                    if (bin > NBINS - 1) bin = NBINS - 1;
                    atomicAdd(&hist[bin - RFLOOR], 1u);
                    if (v >= COLLECT_THR) {
                        float qq  = __fdiv_rn(dd, SIG2F);
                        float tmp = __fadd_rn(1.0f, -qq);
                        tmp = fmaxf(tmp, 0.0f);
                        float vf = __fmul_rn(__fmul_rn(base, tmp), a2v[i][j]);
                        unsigned pos = atomicAdd(&g_ccount, 1u);
                        if (pos < CAP) {
                            g_cval[pos] = vf;
                            g_cidx[pos] = (s * NR + r) * 25 + i * 5 + j;
                        }
                    }
                }
            }
        }
    }
    __syncthreads();
    for (int b = tid; b < NBINS - RFLOOR; b += 256) {
        unsigned c = hist[b];
        if (c) atomicAdd(&g_hist[RFLOOR + b], c);
    }
}

// Threshold from the restricted histogram; full-histogram fallback when the
// 512th value can't be resolved strictly above the floor.
__global__ void thresh_kernel() {
    if (threadIdx.x == 0 && blockIdx.x == 0) {
        unsigned suf = 0; int bstar = -1;
        for (int b = NBINS - 1; b >= RFLOOR; b--) {
            suf += g_hist[b];
            if (suf >= 512) { bstar = b; break; }
        }
        if (bstar <= RFLOOR) {
            g_need_full = 1;
            g_skip = 0;
            return;
        }
        int ba = bstar - 1;             // one-bin slack (>= RFLOOR, counted)
        unsigned cnt = suf + g_hist[ba];
        while (cnt > CAP && ba < NBINS - 1) {
            cnt -= g_hist[ba];
            ba++;
        }
        g_thr = (float)ba * (1.0f / 1024.0f);
        int skip = (ba >= COLLECT_BIN && g_ccount <= CAP) ? 1 : 0;
        g_skip = skip;
        if (!skip) g_ccount = 0;
    }
}

// Conditional full low-bin histogram [0, RFLOOR) — only when unresolved.
__global__ __launch_bounds__(256) void hist_low_kernel(const float* __restrict__ aff) {
    if (!g_need_full) return;
    __shared__ float    rows[KNB][2048];
    __shared__ unsigned hist[RFLOOR];
    __shared__ int      s_sidx[KNB];
    int s = blockIdx.x, tid = threadIdx.x;
    if (tid < KNB) s_sidx[tid] = g_sidx[s * KNB + tid];
    for (int b = tid; b < RFLOOR; b += 256) hist[b] = 0;
    __syncthreads();
#pragma unroll
    for (int i = 0; i < KNB; i++) {
        const float4* srcp = (const float4*)(aff + s_sidx[i] * NR);
        float4* dst = (float4*)rows[i];
        for (int c = tid; c < 512; c += 256) dst[c] = srcp[c];
    }
    float sdv[KNB];
#pragma unroll
    for (int i = 0; i < KNB; i++) sdv[i] = g_sd[s * KNB + i];
    __syncthreads();
    for (int rb = 0; rb < NR; rb += 256) {
        int r = rb + tid;
        float base = aff[s * NR + r];
        float b100 = -100.0f * base;
        float rd[KNB]; int ra[KNB];
#pragma unroll
        for (int j = 0; j < KNB; j++) {
            rd[j] = g_rdT[j * NR + r];
            ra[j] = g_ridxT[j * NR + r];
        }
#pragma unroll
        for (int i = 0; i < KNB; i++) {
#pragma unroll
            for (int j = 0; j < KNB; j++) {
                float d  = sdv[i] - rd[j];
                float bt = __fmaf_rn(__fmul_rn(d, d), b100, base);
                float v  = __fmul_rn(bt, rows[i][ra[j]]);
                if (v > 0.0f && v < GATEF) {
                    int bin = (int)(v * 1024.0f);
                    if (bin < RFLOOR) atomicAdd(&hist[bin], 1u);
                }
            }
        }
    }
    __syncthreads();
    for (int b = tid; b < RFLOOR; b += 256) {
        unsigned c = hist[b];
        if (c) atomicAdd(&g_hist[b], c);
    }
}

// Conditional: re-threshold over the complete histogram.
__global__ void thresh2_kernel() {
    if (threadIdx.x == 0 && blockIdx.x == 0) {
        if (!g_need_full) return;
        unsigned suf = 0; int bstar = -1;
        for (int b = NBINS - 1; b >= 0; b--) {
            suf += g_hist[b];
            if (suf >= 512) { bstar = b; break; }
        }
        if (bstar < 0) bstar = 0;
        int ba = bstar > 0 ? bstar - 1 : 0;
        unsigned cnt = suf + ((ba < bstar) ? g_hist[ba] : 0u);
        while (cnt > CAP && ba < NBINS - 1) {
            cnt -= g_hist[ba];
            ba++;
        }
        g_thr = (float)ba * (1.0f / 1024.0f);
        if (g_thr < 1e-30f) g_thr = 1e-30f;
        g_skip = 0;
        g_ccount = 0;
    }
}

// Fallback collect (usually skipped): admit hot v >= thr, store faithful value.
__global__ __launch_bounds__(256) void collect_kernel(const float* __restrict__ aff) {
    if (g_skip) return;
    __shared__ float rows[KNB][2048];
    __shared__ int   s_sidx[KNB];
    int s = blockIdx.x, tid = threadIdx.x;
    if (tid < KNB) s_sidx[tid] = g_sidx[s * KNB + tid];
    __syncthreads();
#pragma unroll
    for (int i = 0; i < KNB; i++) {
        const float4* srcp = (const float4*)(aff + s_sidx[i] * NR);
        float4* dst = (float4*)rows[i];
        for (int c = tid; c < 512; c += 256) dst[c] = srcp[c];
    }
    float thr = g_thr;
    float sdv[KNB];
#pragma unroll
    for (int i = 0; i < KNB; i++) sdv[i] = g_sd[s * KNB + i];
    __syncthreads();
    for (int rb = 0; rb < NR; rb += 256) {
        int r = rb + tid;
        float base = aff[s * NR + r];
        float b100 = -100.0f * base;
        float rd[KNB]; int ra[KNB];
#pragma unroll
        for (int j = 0; j < KNB; j++) {
            rd[j] = g_rdT[j * NR + r];
            ra[j] = g_ridxT[j * NR + r];
        }
#pragma unroll
        for (int i = 0; i < KNB; i++) {
#pragma unroll
            for (int j = 0; j < KNB; j++) {
                float d  = sdv[i] - rd[j];
                float dd = __fmul_rn(d, d);
                float bt = __fmaf_rn(dd, b100, base);
                if (bt >= thr) {
                    float v = __fmul_rn(bt, rows[i][ra[j]]);
                    if (v >= thr && v > 0.0f) {
                        float qq  = __fdiv_rn(dd, SIG2F);
                        float tmp = __fadd_rn(1.0f, -qq);
                        tmp = fmaxf(tmp, 0.0f);
                        float vf = __fmul_rn(__fmul_rn(base, tmp), rows[i][ra[j]]);
                        unsigned pos = atomicAdd(&g_ccount, 1u);
                        if (pos < CAP) {
                            g_cval[pos] = vf;
                            g_cidx[pos] = (s * NR + r) * 25 + i * 5 + j;
                        }
                    }
                }
            }
        }
    }
}

// Select (unchanged, proven): refine -> bitonic -> emit f32 indices.
__global__ __launch_bounds__(1024) void select_kernel(float* __restrict__ out,
                                                      int out_size) {
    __shared__ unsigned long long keys[KEYS_CAP];
    __shared__ unsigned h2[1024];
    __shared__ unsigned m2;
    __shared__ float sh_thr2;
    int tid = threadIdx.x;
    unsigned M = g_ccount; if (M > CAP) M = CAP;
    float thr = g_thr;
    h2[tid] = 0;
    if (tid == 0) { m2 = 0; sh_thr2 = -1.0f; }
    __syncthreads();
    if (M > KEYS_CAP) {
        float binw2 = (1.0f - thr) * (1.0f / 1024.0f);
        if (binw2 <= 0.0f) binw2 = 1e-9f;
        for (unsigned c = tid; c < M; c += 1024) {
            float v = g_cval[c];
            int b = (int)((v - thr) / binw2);
            if (b < 0) b = 0;
            if (b > 1023) b = 1023;
            atomicAdd(&h2[b], 1u);
        }
        __syncthreads();
        if (tid == 0) {
            unsigned suf = 0; int b2 = 0;
            for (int b = 1023; b >= 0; b--) {
                suf += h2[b];
                if (suf >= 512) { b2 = b; break; }
            }
            int ba = b2;
            unsigned cnt = suf;
            if (ba > 0 && cnt + h2[ba - 1] <= (unsigned)KEYS_CAP) {
                ba--; cnt += h2[ba];
            }
            while (cnt > (unsigned)KEYS_CAP && ba < 1023) {
                cnt -= h2[ba]; ba++;
            }
            sh_thr2 = thr + (float)ba * binw2;
            if (sh_thr2 < thr) sh_thr2 = thr;
        }
        __syncthreads();
    }
    float thr2 = sh_thr2;   // -1 => keep all
    for (unsigned c = tid; c < M; c += 1024) {
        float v = g_cval[c];
        if (v >= thr2) {
            unsigned p = atomicAdd(&m2, 1u);
            if (p < KEYS_CAP) {
                unsigned idx = (unsigned)g_cidx[c];
                if (idx > MAXIDX) idx = MAXIDX;
                keys[p] = ((unsigned long long)__float_as_uint(v) << 32)
                        | (unsigned long long)(0xFFFFFFFFu - idx);
            }
        }
    }
    __syncthreads();
    unsigned M2 = m2; if (M2 > KEYS_CAP) M2 = KEYS_CAP;
    for (unsigned e = M2 + tid; e < KEYS_CAP; e += 1024) keys[e] = 0ull;
    __syncthreads();
    for (unsigned k = 2; k <= KEYS_CAP; k <<= 1) {
        for (unsigned jj = k >> 1; jj > 0; jj >>= 1) {
            for (unsigned e = tid; e < KEYS_CAP; e += 1024) {
                unsigned partner = e ^ jj;
                if (partner > e) {
                    unsigned long long A = keys[e], B = keys[partner];
                    bool desc = ((e & k) == 0);
                    if (desc ? (A < B) : (A > B)) { keys[e] = B; keys[partner] = A; }
                }
            }
            __syncthreads();
        }
    }
    if (tid < 512) {
        unsigned long long key = keys[tid];
        unsigned idx = 0xFFFFFFFFu - (unsigned)(key & 0xFFFFFFFFull);
        if (idx > MAXIDX) idx = MAXIDX;
        int s = (int)(idx / 51200u);  int rem = (int)(idx - (unsigned)s * 51200u);
        int r = rem / 25;             int ij  = rem - r * 25;
        int i = ij / 5;               int j   = ij - i * 5;
        if (s > NS - 1) s = NS - 1;
        if (r > NR - 1) r = NR - 1;
        if (tid < out_size)        out[tid]        = (float)s;
        if (512 + tid < out_size)  out[512 + tid]  = (float)r;
        if (1024 + tid < out_size) out[1024 + tid] = (float)g_sidx[s * KNB + i];
        if (1536 + tid < out_size) out[1536 + tid] = (float)g_ridxT[j * NR + r];
    }
}

extern "C" void kernel_launch(void* const* d_in, const int* in_sizes, int n_in,
                              void* d_out, int out_size) {
    const float *src, *ref, *aff;
    if (in_sizes[0] >= (1 << 20)) {
        aff = (const float*)d_in[0];
        ref = (const float*)d_in[1];
        src = (const float*)d_in[2];
    } else {
        src = (const float*)d_in[0];
        ref = (const float*)d_in[1];
        aff = (const float*)d_in[2];
    }
    float* out = (float*)d_out;

    zero_kernel<<<4, 256>>>();
    knn_kernel<<<(NS + NR) / KNN_QPB, 256>>>(src, ref);
    scan1_kernel<<<NS, 256>>>(aff);
    thresh_kernel<<<1, 32>>>();
    hist_low_kernel<<<NS, 256>>>(aff);   // early-exits unless unresolved
    thresh2_kernel<<<1, 32>>>();         // early-exits unless unresolved
    collect_kernel<<<NS, 256>>>(aff);    // early-exits when skip
    select_kernel<<<1, 1024>>>(out, out_size);
}